// round 9
// baseline (speedup 1.0000x reference)
#include <cuda_runtime.h>
#include <cuda_bf16.h>
#include <math.h>

#define N_FFT 16000
#define M_HALF 8000
#define BATCH 512
#define IN_DIM 2048
#define NTH 1024

// ---------------- scratch (static __device__, no allocation) ----------------
__device__ int    g_h[2 * IN_DIM];
__device__ float  g_s[2 * IN_DIM];
__device__ float2 g_tw[N_FFT];       // W_N^j = exp(-2*pi*i*j/N)
__device__ int    g_isig8[M_HALF];   // natural freq -> scrambled pos (plan 16,10,10,5)
__device__ __align__(16) float g_norm[N_FFT];   // sum |c| -> reciprocal norm
__device__ float2 g_C1[(size_t)BATCH * M_HALF]; // scrambled C1 stash (32 MB)

// ---------------- complex helpers ----------------
__device__ __forceinline__ float2 cmul(float2 a, float2 b) {
    return make_float2(a.x * b.x - a.y * b.y, a.x * b.y + a.y * b.x);
}
__device__ __forceinline__ float2 cmulc(float2 a, float2 b) {  // a * conj(b)
    return make_float2(a.x * b.x + a.y * b.y, a.y * b.x - a.x * b.y);
}
__device__ __forceinline__ float2 cadd(float2 a, float2 b) {
    return make_float2(a.x + b.x, a.y + b.y);
}
__device__ __forceinline__ float2 csub(float2 a, float2 b) {
    return make_float2(a.x - b.x, a.y - b.y);
}
__device__ __forceinline__ float2 mul_negi(float2 a) { return make_float2(a.y, -a.x); }
__device__ __forceinline__ float2 mul_posi(float2 a) { return make_float2(-a.y, a.x); }

// W5^j
__constant__ float2 W5c[5] = {
    { 1.0f,                  0.0f                 },
    { 0.30901699437494742f, -0.95105651629515357f },
    {-0.80901699437494742f, -0.58778525229247314f },
    {-0.80901699437494745f,  0.58778525229247312f },
    { 0.30901699437494740f,  0.95105651629515364f }
};
// W10^m, m=0..4
__constant__ float2 W10c[5] = {
    { 1.0f,                  0.0f                 },
    { 0.80901699437494742f, -0.58778525229247312f },
    { 0.30901699437494742f, -0.95105651629515357f },
    {-0.30901699437494742f, -0.95105651629515357f },
    {-0.80901699437494742f, -0.58778525229247312f }
};

#define C_S2 0.70710678118654752440f
#define C16A 0.92387953251128676f
#define C16B 0.38268343236508977f

// ---------------- small DFTs in registers ----------------
#define DFT4F(a,b,c,d,o0,o1,o2,o3) do { \
    float2 _t0 = cadd(a,c), _t1 = csub(a,c); \
    float2 _t2 = cadd(b,d), _t3 = mul_negi(csub(b,d)); \
    o0 = cadd(_t0,_t2); o1 = cadd(_t1,_t3); \
    o2 = csub(_t0,_t2); o3 = csub(_t1,_t3); } while(0)
#define DFT4I(a,b,c,d,o0,o1,o2,o3) do { \
    float2 _t0 = cadd(a,c), _t1 = csub(a,c); \
    float2 _t2 = cadd(b,d), _t3 = mul_posi(csub(b,d)); \
    o0 = cadd(_t0,_t2); o1 = cadd(_t1,_t3); \
    o2 = csub(_t0,_t2); o3 = csub(_t1,_t3); } while(0)

__device__ __forceinline__ void dft16(float2 x[16]) {
    float2 A0[4], A1[4], A2[4], A3[4];
    DFT4F(x[0], x[4], x[8],  x[12], A0[0], A0[1], A0[2], A0[3]);
    DFT4F(x[1], x[5], x[9],  x[13], A1[0], A1[1], A1[2], A1[3]);
    DFT4F(x[2], x[6], x[10], x[14], A2[0], A2[1], A2[2], A2[3]);
    DFT4F(x[3], x[7], x[11], x[15], A3[0], A3[1], A3[2], A3[3]);
    A1[1] = cmul(A1[1], make_float2( C16A, -C16B));
    A1[2] = cmul(A1[2], make_float2( C_S2, -C_S2));
    A1[3] = cmul(A1[3], make_float2( C16B, -C16A));
    A2[1] = cmul(A2[1], make_float2( C_S2, -C_S2));
    A2[2] = mul_negi(A2[2]);
    A2[3] = cmul(A2[3], make_float2(-C_S2, -C_S2));
    A3[1] = cmul(A3[1], make_float2( C16B, -C16A));
    A3[2] = cmul(A3[2], make_float2(-C_S2, -C_S2));
    A3[3] = cmul(A3[3], make_float2(-C16A,  C16B));
#pragma unroll
    for (int m = 0; m < 4; m++)
        DFT4F(A0[m], A1[m], A2[m], A3[m], x[m], x[m+4], x[m+8], x[m+12]);
}

__device__ __forceinline__ void idft16(float2 x[16]) {
    float2 A0[4], A1[4], A2[4], A3[4];
    DFT4I(x[0], x[4], x[8],  x[12], A0[0], A0[1], A0[2], A0[3]);
    DFT4I(x[1], x[5], x[9],  x[13], A1[0], A1[1], A1[2], A1[3]);
    DFT4I(x[2], x[6], x[10], x[14], A2[0], A2[1], A2[2], A2[3]);
    DFT4I(x[3], x[7], x[11], x[15], A3[0], A3[1], A3[2], A3[3]);
    A1[1] = cmul(A1[1], make_float2( C16A,  C16B));
    A1[2] = cmul(A1[2], make_float2( C_S2,  C_S2));
    A1[3] = cmul(A1[3], make_float2( C16B,  C16A));
    A2[1] = cmul(A2[1], make_float2( C_S2,  C_S2));
    A2[2] = mul_posi(A2[2]);
    A2[3] = cmul(A2[3], make_float2(-C_S2,  C_S2));
    A3[1] = cmul(A3[1], make_float2( C16B,  C16A));
    A3[2] = cmul(A3[2], make_float2(-C_S2,  C_S2));
    A3[3] = cmul(A3[3], make_float2(-C16A, -C16B));
#pragma unroll
    for (int m = 0; m < 4; m++)
        DFT4I(A0[m], A1[m], A2[m], A3[m], x[m], x[m+4], x[m+8], x[m+12]);
}

__device__ __forceinline__ void dft5f(float2 a0, float2 a1, float2 a2,
                                      float2 a3, float2 a4, float2 o[5]) {
#pragma unroll
    for (int p = 0; p < 5; p++) {
        float2 acc = a0;
        acc = cadd(acc, cmul(a1, W5c[p % 5]));
        acc = cadd(acc, cmul(a2, W5c[(2*p) % 5]));
        acc = cadd(acc, cmul(a3, W5c[(3*p) % 5]));
        acc = cadd(acc, cmul(a4, W5c[(4*p) % 5]));
        o[p] = acc;
    }
}
__device__ __forceinline__ void dft5i(float2 a0, float2 a1, float2 a2,
                                      float2 a3, float2 a4, float2 o[5]) {
#pragma unroll
    for (int p = 0; p < 5; p++) {
        float2 acc = a0;
        acc = cadd(acc, cmulc(a1, W5c[p % 5]));
        acc = cadd(acc, cmulc(a2, W5c[(2*p) % 5]));
        acc = cadd(acc, cmulc(a3, W5c[(3*p) % 5]));
        acc = cadd(acc, cmulc(a4, W5c[(4*p) % 5]));
        o[p] = acc;
    }
}

__device__ __forceinline__ void dft10(float2 x[10]) {
    float2 B0[5], B1[5];
    dft5f(x[0], x[2], x[4], x[6], x[8], B0);
    dft5f(x[1], x[3], x[5], x[7], x[9], B1);
#pragma unroll
    for (int m = 0; m < 5; m++) {
        float2 t = cmul(B1[m], W10c[m]);
        x[m]     = cadd(B0[m], t);
        x[m + 5] = csub(B0[m], t);
    }
}
__device__ __forceinline__ void idft10(float2 x[10]) {
    float2 B0[5], B1[5];
    dft5i(x[0], x[2], x[4], x[6], x[8], B0);
    dft5i(x[1], x[3], x[5], x[7], x[9], B1);
#pragma unroll
    for (int m = 0; m < 5; m++) {
        float2 t = cmulc(B1[m], W10c[m]);
        x[m]     = cadd(B0[m], t);
        x[m + 5] = csub(B0[m], t);
    }
}

// ---------------- forward FFT stages, 8000 pts (DIF plan: 16,10,10,5) ------
// All twiddles via direct g_tw indexing (max index < 16000, verified).

__device__ __forceinline__ void stage16_fwd8(float2* sm) {
    const int h = 500;
    for (int t = threadIdx.x; t < h; t += NTH) {
        float2* b = sm + t;
        float2 x[16];
#pragma unroll
        for (int q = 0; q < 16; q++) x[q] = b[q * h];
        dft16(x);
        b[0] = x[0];
#pragma unroll
        for (int p = 1; p < 16; p++) b[p * h] = cmul(x[p], g_tw[2 * t * p]);
    }
    __syncthreads();
}

template<int NS, int TWS>   // TWS = 16000 / NS
__device__ __forceinline__ void stage10_fwd8(float2* sm) {
    const int h = NS / 10;
    for (int u = threadIdx.x; u < M_HALF / 10; u += NTH) {
        int blk = u / h, t = u - blk * h;
        float2* b = sm + blk * NS + t;
        float2 x[10];
#pragma unroll
        for (int q = 0; q < 10; q++) x[q] = b[q * h];
        dft10(x);
        b[0] = x[0];
#pragma unroll
        for (int p = 1; p < 10; p++) b[p * h] = cmul(x[p], g_tw[TWS * t * p]);
    }
    __syncthreads();
}

// last forward stage, result to smem (C2)
__device__ __forceinline__ void stage5_fwd8(float2* sm) {
    for (int u = threadIdx.x; u < M_HALF / 5; u += NTH) {
        float2* b = sm + u * 5;
        float2 o[5];
        dft5f(b[0], b[1], b[2], b[3], b[4], o);
#pragma unroll
        for (int q = 0; q < 5; q++) b[q] = o[q];
    }
    __syncthreads();
}

// last forward stage, result streamed to gmem stash (C1)
__device__ __forceinline__ void stage5_fwd8_gmem(const float2* sm, float2* dst) {
    for (int u = threadIdx.x; u < M_HALF / 5; u += NTH) {
        const float2* b = sm + u * 5;
        float2 o[5];
        dft5f(b[0], b[1], b[2], b[3], b[4], o);
#pragma unroll
        for (int q = 0; q < 5; q++) dst[u * 5 + q] = o[q];
    }
    __syncthreads();   // smem reads must complete before buffer reuse
}

// ---------------- inverse FFT stages, 8000 pts (mirrored DIT) --------------
__device__ __forceinline__ void stage5_inv8(float2* Y) {
    for (int u = threadIdx.x; u < M_HALF / 5; u += NTH) {
        float2* b = Y + u * 5;
        float2 o[5];
        dft5i(b[0], b[1], b[2], b[3], b[4], o);
#pragma unroll
        for (int q = 0; q < 5; q++) b[q] = o[q];
    }
    __syncthreads();
}

template<int NS, int TWS>
__device__ __forceinline__ void stage10_inv8(float2* Y) {
    const int h = NS / 10;
    for (int u = threadIdx.x; u < M_HALF / 10; u += NTH) {
        int blk = u / h, t = u - blk * h;
        float2* b = Y + blk * NS + t;
        float2 y[10];
        y[0] = b[0];
#pragma unroll
        for (int p = 1; p < 10; p++) y[p] = cmulc(b[p * h], g_tw[TWS * t * p]);
        idft10(y);
#pragma unroll
        for (int q = 0; q < 10; q++) b[q * h] = y[q];
    }
    __syncthreads();
}

// Final inverse stage fused with de-interleave, signed-sqrt store, norm REDG.
__device__ __forceinline__ void stage16_inv_store8(float2* Y, float* dst) {
    const int h = 500;
    float2* dst2 = (float2*)dst;
    for (int t = threadIdx.x; t < h; t += NTH) {
        float2* b = Y + t;
        float2 y[16];
        y[0] = b[0];
#pragma unroll
        for (int p = 1; p < 16; p++) y[p] = cmulc(b[p * h], g_tw[2 * t * p]);
        idft16(y);
#pragma unroll
        for (int q = 0; q < 16; q++) {
            int m = q * 500 + t;           // y[m] = x[2m] + i x[2m+1]
            float c0 = y[q].x, c1 = y[q].y;
            float a0 = fabsf(c0), a1 = fabsf(c1);
            dst2[m] = make_float2(copysignf(sqrtf(a0), c0),
                                  copysignf(sqrtf(a1), c1));
            atomicAdd(&g_norm[2 * m],     a0);   // ss^2 == |c| exactly
            atomicAdd(&g_norm[2 * m + 1], a1);
        }
    }
}

// ------- extract (one block per sketch row) + fused one-time setup ---------
__global__ void k_extract(const float* __restrict__ sk1,
                          const float* __restrict__ sk2) {
    int r = blockIdx.x;

    if (threadIdx.x < 4) {
        int j = r * 4 + threadIdx.x;
        if (j < N_FFT) {
            double a = -2.0 * 3.14159265358979323846 * (double)j / (double)N_FFT;
            double sn, cs;
            sincos(a, &sn, &cs);
            g_tw[j] = make_float2((float)cs, (float)sn);
            g_norm[j] = 0.f;
            if (j < M_HALF) {
                // isig8 for plan {16,10,10,5}
                int q0 = j / 500, r8 = j - q0 * 500;
                int q1 = r8 / 50; r8 -= q1 * 50;
                int q2 = r8 / 5,  q3 = r8 - q2 * 5;
                g_isig8[q0 + 16 * (q1 + 10 * (q2 + 10 * q3))] = j;
            }
        }
    }

    const float* row = (r < IN_DIM) ? (sk1 + (size_t)r * N_FFT)
                                    : (sk2 + (size_t)(r - IN_DIM) * N_FFT);
    const float4* row4 = (const float4*)row;
    __shared__ int found;
    if (threadIdx.x == 0) found = 0;
    __syncthreads();
    for (int base = 0; base < N_FFT / 4; base += blockDim.x) {
        int j = base + threadIdx.x;
        if (j < N_FFT / 4) {
            float4 v = row4[j];
            if (v.x != 0.f || v.y != 0.f || v.z != 0.f || v.w != 0.f) {
                int   c   = (v.x != 0.f) ? 0 : (v.y != 0.f) ? 1 : (v.z != 0.f) ? 2 : 3;
                float val = (c == 0) ? v.x : (c == 1) ? v.y : (c == 2) ? v.z : v.w;
                g_h[r] = 4 * j + c;
                g_s[r] = val;
                found = 1;
            }
        }
        __syncthreads();
        if (found) break;
    }
}

// ---------------- fused main kernel (64 KB smem -> 2 CTAs/SM) --------------
__global__ void __launch_bounds__(NTH, 1)
k_main(const float* __restrict__ x1, const float* __restrict__ x2,
       float* __restrict__ out) {
    extern __shared__ float2 sm[];
    float* smf = (float*)sm;
    int b = blockIdx.x;
    float2* C1 = g_C1 + (size_t)b * M_HALF;

    // ---- phase 1: c1[m] = p1[2m] + i p1[2m+1] ----
    float4* sm4 = (float4*)sm;
    for (int i = threadIdx.x; i < M_HALF / 2; i += NTH)
        sm4[i] = make_float4(0.f, 0.f, 0.f, 0.f);
    __syncthreads();
    const float* r1 = x1 + (size_t)b * IN_DIM;
    for (int k = threadIdx.x; k < IN_DIM; k += NTH)
        atomicAdd(smf + g_h[k], g_s[k] * r1[k]);   // float index == h
    __syncthreads();

    stage16_fwd8(sm);
    stage10_fwd8<500, 32>(sm);
    stage10_fwd8<50, 320>(sm);
    stage5_fwd8_gmem(sm, C1);     // scrambled C1 -> gmem stash

    // ---- phase 2: c2 ----
    for (int i = threadIdx.x; i < M_HALF / 2; i += NTH)
        sm4[i] = make_float4(0.f, 0.f, 0.f, 0.f);
    __syncthreads();
    const float* r2 = x2 + (size_t)b * IN_DIM;
    for (int k = threadIdx.x; k < IN_DIM; k += NTH)
        atomicAdd(smf + g_h[IN_DIM + k], g_s[IN_DIM + k] * r2[k]);
    __syncthreads();

    stage16_fwd8(sm);
    stage10_fwd8<500, 32>(sm);
    stage10_fwd8<50, 320>(sm);
    stage5_fwd8(sm);              // scrambled C2 stays in smem

    // ---- pairing: Hermitian split of C1,C2 -> F1,F2 ; G = F1*F2 ;
    //      irfft half-size packing Y, written in-place (slot-pair per thread).
    for (int k = threadIdx.x; k <= 4000; k += NTH) {
        if (k == 0) {
            int j0 = g_isig8[0];
            float2 c1 = C1[j0], c2 = sm[j0];
            float F1_0 = c1.x + c1.y, F1_8 = c1.x - c1.y;
            float F2_0 = c2.x + c2.y, F2_8 = c2.x - c2.y;
            float G0 = F1_0 * F2_0, G8 = F1_8 * F2_8;
            sm[j0] = make_float2(G0 + G8, G0 - G8);
        } else if (k == 4000) {
            int j = g_isig8[4000];
            float2 c1 = C1[j], c2 = sm[j];
            float2 F1 = make_float2(c1.x, -c1.y);   // conj(C[4000])
            float2 F2 = make_float2(c2.x, -c2.y);
            float2 G = cmul(F1, F2);
            sm[j] = make_float2(2.f * G.x, -2.f * G.y);
        } else {
            int jk = g_isig8[k], jm = g_isig8[M_HALF - k];
            float2 c1k = C1[jk], c1m = C1[jm];
            float2 c2k = sm[jk], c2m = sm[jm];
            float2 W = g_tw[k];
            // signal 1 split: E=(Ck+conj(Cm))/2, O=-i(Ck-conj(Cm))/2
            float2 E1 = make_float2(0.5f * (c1k.x + c1m.x), 0.5f * (c1k.y - c1m.y));
            float2 O1 = make_float2(0.5f * (c1k.y + c1m.y), -0.5f * (c1k.x - c1m.x));
            float2 WO1 = cmul(W, O1);
            float2 F1k = cadd(E1, WO1);
            float2 F1m = make_float2(E1.x - WO1.x, -(E1.y - WO1.y)); // conj(E1-WO1)
            // signal 2
            float2 E2 = make_float2(0.5f * (c2k.x + c2m.x), 0.5f * (c2k.y - c2m.y));
            float2 O2 = make_float2(0.5f * (c2k.y + c2m.y), -0.5f * (c2k.x - c2m.x));
            float2 WO2 = cmul(W, O2);
            float2 F2k = cadd(E2, WO2);
            float2 F2m = make_float2(E2.x - WO2.x, -(E2.y - WO2.y));
            float2 Gk = cmul(F1k, F2k);
            float2 Gm = cmul(F1m, F2m);
            float2 cGm = make_float2(Gm.x, -Gm.y);
            float2 cGk = make_float2(Gk.x, -Gk.y);
            // Y[k]
            float2 A1 = cadd(Gk, cGm);
            float2 B1 = cmulc(csub(Gk, cGm), W);     // * e^{+2pi i k/N}
            sm[jk] = cadd(A1, mul_posi(B1));
            // Y[8000-k]  (e^{+2pi i (8000-k)/N} = -W)
            float2 A2 = cadd(Gm, cGk);
            float2 t2 = cmul(csub(Gm, cGk), W);
            sm[jm] = cadd(A2, mul_posi(make_float2(-t2.x, -t2.y)));
        }
    }
    __syncthreads();

    // ---- inverse 8000-pt (natural order) + fused de-interleave/store ----
    stage5_inv8(sm);
    stage10_inv8<50, 320>(sm);
    stage10_inv8<500, 32>(sm);
    stage16_inv_store8(sm, out + (size_t)b * N_FFT);
}

// turn accumulated sums into reciprocal norms (in place)
__global__ void k_rnorm() {
    int d = blockIdx.x * blockDim.x + threadIdx.x;
    if (d < N_FFT)
        g_norm[d] = 1.0f / fmaxf(sqrtf(g_norm[d]), 1e-12f);
}

__global__ void k_normalize(float* __restrict__ out) {
    int c4 = blockIdx.x * blockDim.x + threadIdx.x;
    if (c4 >= N_FFT / 4) return;
    int b = blockIdx.y;
    float4 nv = ((const float4*)g_norm)[c4];
    float4* o4 = (float4*)out + (size_t)b * (N_FFT / 4) + c4;
    float4 v = *o4;
    v.x *= nv.x; v.y *= nv.y; v.z *= nv.z; v.w *= nv.w;
    *o4 = v;
}

// ---------------- launch ----------------
extern "C" void kernel_launch(void* const* d_in, const int* in_sizes, int n_in,
                              void* d_out, int out_size) {
    const float* x1  = (const float*)d_in[0];
    const float* x2  = (const float*)d_in[1];
    const float* sk1 = (const float*)d_in[2];
    const float* sk2 = (const float*)d_in[3];
    float* out = (float*)d_out;

    const int smem = M_HALF * sizeof(float2);   // 64000 B -> 2 CTAs/SM
    cudaFuncSetAttribute(k_main, cudaFuncAttributeMaxDynamicSharedMemorySize, smem);

    k_extract<<<2 * IN_DIM, 512>>>(sk1, sk2);
    k_main<<<BATCH, NTH, smem>>>(x1, x2, out);
    k_rnorm<<<(N_FFT + 255) / 256, 256>>>();
    dim3 ng((N_FFT / 4 + 255) / 256, BATCH);
    k_normalize<<<ng, 256>>>(out);
}